// round 16
// baseline (speedup 1.0000x reference)
#include <cuda_runtime.h>
#include <cstdint>

// out[b, n, :] = (cnn[b] @ Wkv[:, 768:1536]) @ Wp + bp   (independent of n)
// image_patches and Wq are dead: softmax over kv_len=1 -> attn == 1.
//
// 3 launches chained with PDL:
//   gemm1: 384 CTAs x 256 thr (12 n-tiles x 32 k-splits of 64), one-phase
//          smem staging with DUP-A (A stored as replicated f32x2 pairs so the
//          inner loop is 3 LDS.128 + 8 FFMA2, no pack MOVs), red.v4 -> g_v
//          (zero on entry: static init call 1, re-zeroed by bcast each call).
//          Prologue: g_y = bias.
//   gemm2: 192 CTAs x 256 thr (12 n-tiles x 16 k-splits of 48); Wp loads
//          before cudaGridDependencySynchronize(), same dup-A body,
//          red.v4 -> bias-preloaded g_y.
//   bcast: 576 CTAs x 512 thr, 8 TMA bulk stores of 24 KB; zeroes g_v at end.

#define B_SZ   64
#define N_SEQ  576
#define C_DIM  768
#define K1     2048
#define LDKV   1536

#define NT1    12              // gemm1: 12 n-tiles of 64
#define KS1    32              // gemm1: 32 k-splits of 64 -> 384 blocks
#define KC1    64
#define NT2    12              // gemm2: 12 n-tiles of 64
#define KS2    16              // gemm2: 16 k-splits of 48 -> 192 blocks
#define KC2    48

__device__ float g_v[B_SZ * C_DIM];   // zero on entry to every call
__device__ float g_y[B_SZ * C_DIM];   // set to bias by gemm1 every call

// ---- packed f32x2 (FFMA2) ----
__device__ __forceinline__ unsigned long long pack2(float x) {
    unsigned long long r; unsigned xi = __float_as_uint(x);
    asm("mov.b64 %0, {%1, %1};" : "=l"(r) : "r"(xi));
    return r;
}
__device__ __forceinline__ void fma2(unsigned long long& d,
                                     unsigned long long a, unsigned long long b) {
    asm("fma.rn.f32x2 %0, %1, %2, %0;" : "+l"(d) : "l"(a), "l"(b));
}
__device__ __forceinline__ float2 u2f(unsigned long long u) {
    float2 f; asm("mov.b64 {%0, %1}, %2;" : "=f"(f.x), "=f"(f.y) : "l"(u));
    return f;
}
// Vector reduction: 1 LTS atomic op for 4 floats (sm_90+).
__device__ __forceinline__ void redg_add4(float* p, float a, float b, float c, float d) {
    asm volatile("red.global.add.v4.f32 [%0], {%1, %2, %3, %4};"
                 :: "l"(p), "f"(a), "f"(b), "f"(c), "f"(d) : "memory");
}
__device__ __forceinline__ uint32_t smem_u32(const void* p) {
    uint32_t a;
    asm("{ .reg .u64 t; cvta.to.shared.u64 t, %1; cvt.u32.u64 %0, t; }" : "=r"(a) : "l"(p));
    return a;
}

// ---------------------------------------------------------------------------
// FFMA2 compute loop, dup-A variant: As2[k][m] = (A[m][k], A[m][k]) as f32x2.
// Per k-step per thread: 2x LDS.128 (A pairs) + 1x LDS.128 (B) + 8x FFMA2.
// No pack MOVs in the loop; LDS feeds FFMA2 directly.
// ---------------------------------------------------------------------------
template<int KCHUNK>
__device__ __forceinline__ void compute_loop_dup(
    const unsigned long long (*As2)[66], const float (*Bs)[64],
    unsigned long long acc[4][2])
{
    const int tid = threadIdx.x;
    const int tx = tid & 15, ty = tid >> 4;
    #pragma unroll 8
    for (int k = 0; k < KCHUNK; ++k) {
        ulonglong2 a01 = *(const ulonglong2*)&As2[k][ty * 4];      // (a0,a0),(a1,a1)
        ulonglong2 a23 = *(const ulonglong2*)&As2[k][ty * 4 + 2];  // (a2,a2),(a3,a3)
        ulonglong2 b   = *(const ulonglong2*)&Bs[k][tx * 4];
        fma2(acc[0][0], a01.x, b.x); fma2(acc[0][1], a01.x, b.y);
        fma2(acc[1][0], a01.y, b.x); fma2(acc[1][1], a01.y, b.y);
        fma2(acc[2][0], a23.x, b.x); fma2(acc[2][1], a23.x, b.y);
        fma2(acc[3][0], a23.y, b.x); fma2(acc[3][1], a23.y, b.y);
    }
}

// Shared epilogue: 4 rows x 4 cols per thread -> 4x red.v4.
__device__ __forceinline__ void epilogue_red(
    float* dst, int n0, unsigned long long acc[4][2])
{
    const int tid = threadIdx.x;
    const int tx = tid & 15, ty = tid >> 4;
    #pragma unroll
    for (int i = 0; i < 4; ++i) {
        float2 f0 = u2f(acc[i][0]);
        float2 f1 = u2f(acc[i][1]);
        redg_add4(dst + (ty * 4 + i) * C_DIM + n0 + tx * 4,
                  f0.x, f0.y, f1.x, f1.y);
    }
}

// GEMM1: cnn[64,2048] @ Wkv[:,768:1536], 384 blocks, red.v4 epilogue -> g_v.
// One-phase dup-A staging. Prologue (first 192 blocks): g_y = bias.
__global__ void __launch_bounds__(256, 2)
gemm1_kernel(const float* __restrict__ cnn, const float* __restrict__ Wkv,
             const float* __restrict__ bp)
{
    __shared__ unsigned long long As2[KC1][66];   // 33.8 KB (dup-A pairs)
    __shared__ float Bs[KC1][64];                 // 16 KB

    const int tid = threadIdx.x;
    if (blockIdx.x < 192 && tid < 64) {
        int idx = blockIdx.x * 64 + tid;                  // 12288 float4 of g_y
        ((float4*)g_y)[idx] = ((const float4*)bp)[idx % (C_DIM / 4)];
    }

    int ntile = blockIdx.x % NT1;
    int split = blockIdx.x / NT1;
    int n0 = ntile * 64;
    const float* A  = cnn + split * KC1;                                 // lda K1
    const float* Bm = Wkv + (size_t)(split * KC1) * LDKV + C_DIM + n0;   // ldb LDKV

    constexpr int NV = (64 * KC1) / 4;     // 1024 float4 per operand
    constexpr int PT = NV / 256;           // 4 per thread

    float4 aR[PT], bR[PT];
    #pragma unroll
    for (int i = 0; i < PT; ++i) {
        int idx = tid + i * 256;
        int am = idx / (KC1 / 4);
        int ak = (idx % (KC1 / 4)) * 4;
        aR[i] = *(const float4*)&A[am * K1 + ak];
        int bk = idx >> 4;
        int bn = (idx & 15) * 4;
        bR[i] = *(const float4*)&Bm[bk * LDKV + bn];
    }
    #pragma unroll
    for (int i = 0; i < PT; ++i) {
        int idx = tid + i * 256;
        int am = idx / (KC1 / 4);
        int ak = (idx % (KC1 / 4)) * 4;
        As2[ak + 0][am] = pack2(aR[i].x);
        As2[ak + 1][am] = pack2(aR[i].y);
        As2[ak + 2][am] = pack2(aR[i].z);
        As2[ak + 3][am] = pack2(aR[i].w);
        int bk = idx >> 4;
        int bn = (idx & 15) * 4;
        *(float4*)&Bs[bk][bn] = bR[i];
    }
    __syncthreads();

    unsigned long long acc[4][2];
    #pragma unroll
    for (int i = 0; i < 4; ++i) { acc[i][0] = 0ull; acc[i][1] = 0ull; }
    compute_loop_dup<KC1>(As2, Bs, acc);
    epilogue_red(g_v, n0, acc);

    if (tid == 0) cudaTriggerProgrammaticLaunchCompletion();
}

// GEMM2: v[64,768] @ Wp, 192 blocks. PDL: Wp loads before the dependency
// sync; g_v loads after. Same dup-A body.
__global__ void __launch_bounds__(256, 2)
gemm2_kernel(const float* __restrict__ Wp)
{
    __shared__ unsigned long long As2[KC2][66];   // 25.3 KB
    __shared__ float Bs[KC2][64];                 // 12 KB

    const int tid = threadIdx.x;
    int ntile = blockIdx.x % NT2;
    int split = blockIdx.x / NT2;
    int n0 = ntile * 64;
    const float* Bm = Wp + (size_t)(split * KC2) * C_DIM + n0;

    constexpr int NV = (64 * KC2) / 4;     // 768 float4 per operand
    constexpr int PT = NV / 256;           // 3 per thread

    // --- pre-sync: load Wp tile (independent of gemm1's output) ---
    float4 bR[PT];
    #pragma unroll
    for (int i = 0; i < PT; ++i) {
        int idx = tid + i * 256;
        int bk = idx >> 4;
        int bn = (idx & 15) * 4;
        bR[i] = *(const float4*)&Bm[bk * C_DIM + bn];
    }

    cudaGridDependencySynchronize();       // wait for gemm1's g_v

    const float* A = g_v + split * KC2;
    float4 aR[PT];
    #pragma unroll
    for (int i = 0; i < PT; ++i) {
        int idx = tid + i * 256;
        int am = idx / (KC2 / 4);
        int ak = (idx % (KC2 / 4)) * 4;
        aR[i] = *(const float4*)&A[am * C_DIM + ak];
    }
    #pragma unroll
    for (int i = 0; i < PT; ++i) {
        int idx = tid + i * 256;
        int am = idx / (KC2 / 4);
        int ak = (idx % (KC2 / 4)) * 4;
        As2[ak + 0][am] = pack2(aR[i].x);
        As2[ak + 1][am] = pack2(aR[i].y);
        As2[ak + 2][am] = pack2(aR[i].z);
        As2[ak + 3][am] = pack2(aR[i].w);
        int bk = idx >> 4;
        int bn = (idx & 15) * 4;
        *(float4*)&Bs[bk][bn] = bR[i];
    }
    __syncthreads();

    unsigned long long acc[4][2];
    #pragma unroll
    for (int i = 0; i < 4; ++i) { acc[i][0] = 0ull; acc[i][1] = 0ull; }
    compute_loop_dup<KC2>(As2, Bs, acc);
    epilogue_red(g_y, n0, acc);

    if (tid == 0) cudaTriggerProgrammaticLaunchCompletion();
}

// Broadcast g_y over N=576 via TMA bulk stores; zero g_v for the next call.
// 576 blocks x 512 threads; PDL-synced against gemm2.
__global__ void __launch_bounds__(512)
bcast_kernel(float* __restrict__ out)
{
    __shared__ __align__(16) float ys[8 * C_DIM];   // 24 KB

    int b     = blockIdx.x / 9;
    int chunk = blockIdx.x % 9;
    const int tid = threadIdx.x;

    cudaGridDependencySynchronize();       // wait for gemm2's g_y

    const float4* ysrc = (const float4*)(g_y + b * C_DIM);
    #pragma unroll
    for (int i = tid; i < 8 * (C_DIM / 4); i += 512)
        ((float4*)ys)[i] = ysrc[i % (C_DIM / 4)];
    __syncthreads();
    asm volatile("fence.proxy.async.shared::cta;" ::: "memory");

    if (tid < 8) {
        uint32_t s = smem_u32(ys);
        float* g = out + ((size_t)b * N_SEQ + chunk * 64 + tid * 8) * C_DIM;
        asm volatile("cp.async.bulk.global.shared::cta.bulk_group [%0], [%1], %2;"
                     :: "l"(g), "r"(s), "n"(8 * C_DIM * 4) : "memory");
        asm volatile("cp.async.bulk.commit_group;" ::: "memory");
        asm volatile("cp.async.bulk.wait_group 0;" ::: "memory");
    }

    // zero g_v for the next call (first 192 blocks cover 12288 float4)
    if (blockIdx.x < 192 && tid < 64) {
        ((float4*)g_v)[blockIdx.x * 64 + tid] = make_float4(0.f, 0.f, 0.f, 0.f);
    }
}

extern "C" void kernel_launch(void* const* d_in, const int* in_sizes, int n_in,
                              void* d_out, int out_size)
{
    (void)in_sizes; (void)n_in; (void)out_size;
    // Inputs: image_patches, cnn_feature_vector, Wq, Wkv, Wp, bp
    const float* cnn = (const float*)d_in[1];
    const float* Wkv = (const float*)d_in[3];
    const float* Wp  = (const float*)d_in[4];
    const float* bp  = (const float*)d_in[5];
    float* out = (float*)d_out;

    gemm1_kernel<<<NT1 * KS1, 256>>>(cnn, Wkv, bp);   // 384 blocks

    cudaLaunchAttribute attr[1];
    attr[0].id = cudaLaunchAttributeProgrammaticStreamSerialization;
    attr[0].val.programmaticStreamSerializationAllowed = 1;

    {   // gemm2 with PDL
        cudaLaunchConfig_t cfg = {};
        cfg.gridDim  = dim3(NT2 * KS2, 1, 1);          // 192 blocks
        cfg.blockDim = dim3(256, 1, 1);
        cfg.attrs = attr;
        cfg.numAttrs = 1;
        cudaLaunchKernelEx(&cfg, gemm2_kernel, Wp);
    }
    {   // bcast with PDL
        cudaLaunchConfig_t cfg = {};
        cfg.gridDim  = dim3(B_SZ * 9, 1, 1);           // 576 blocks
        cfg.blockDim = dim3(512, 1, 1);
        cfg.attrs = attr;
        cfg.numAttrs = 1;
        cudaLaunchKernelEx(&cfg, bcast_kernel, out);
    }
}

// round 17
// speedup vs baseline: 1.1739x; 1.1739x over previous
#include <cuda_runtime.h>
#include <cstdint>

// out[b, n, :] = (cnn[b] @ Wkv[:, 768:1536]) @ Wp + bp   (independent of n)
// image_patches and Wq are dead: softmax over kv_len=1 -> attn == 1.
//
// 3 launches chained with PDL. GEMMs use 3xTF32 split-precision tensor-core
// mma (m16n8k8): acc += Ahi*Bhi + Alo*Bhi + Ahi*Blo  (rel_err ~1e-6).
//   gemm1: 384 CTAs x 256 thr (12 n-tiles x 32 k-splits of 64), red.v2 -> g_v
//          (zero on entry: static init call 1, re-zeroed by bcast each call).
//          Prologue: g_y = bias.
//   gemm2: 192 CTAs x 256 thr (12 n-tiles x 16 k-splits of 48), red.v2 -> g_y.
//   bcast: 576 CTAs x 512 thr, 8 TMA bulk stores of 24 KB; zeroes g_v at end.

#define B_SZ   64
#define N_SEQ  576
#define C_DIM  768
#define K1     2048
#define LDKV   1536

#define NT1    12              // gemm1: 12 n-tiles of 64
#define KS1    32              // gemm1: 32 k-splits of 64 -> 384 blocks
#define KC1    64
#define NT2    12              // gemm2: 12 n-tiles of 64
#define KS2    16              // gemm2: 16 k-splits of 48 -> 192 blocks
#define KC2    48

__device__ float g_v[B_SZ * C_DIM];   // zero on entry to every call
__device__ float g_y[B_SZ * C_DIM];   // set to bias by gemm1 every call

// ---- tf32 helpers ----
__device__ __forceinline__ uint32_t to_tf32(float x) {
    uint32_t r; asm("cvt.rna.tf32.f32 %0, %1;" : "=r"(r) : "f"(x)); return r;
}
__device__ __forceinline__ void split_tf32(float x, uint32_t& hi, uint32_t& lo) {
    hi = to_tf32(x);
    lo = to_tf32(x - __uint_as_float(hi));
}
__device__ __forceinline__ void mma_tf32(float c[4],
    uint32_t a0, uint32_t a1, uint32_t a2, uint32_t a3,
    uint32_t b0, uint32_t b1)
{
    asm volatile("mma.sync.aligned.m16n8k8.row.col.f32.tf32.tf32.f32 "
        "{%0,%1,%2,%3}, {%4,%5,%6,%7}, {%8,%9}, {%0,%1,%2,%3};"
        : "+f"(c[0]), "+f"(c[1]), "+f"(c[2]), "+f"(c[3])
        : "r"(a0), "r"(a1), "r"(a2), "r"(a3), "r"(b0), "r"(b1));
}
// Vector reduction (pair): 1 LTS atomic op for 2 floats.
__device__ __forceinline__ void redg_add2(float* p, float a, float b) {
    asm volatile("red.global.add.v2.f32 [%0], {%1, %2};"
                 :: "l"(p), "f"(a), "f"(b) : "memory");
}
__device__ __forceinline__ uint32_t smem_u32(const void* p) {
    uint32_t a;
    asm("{ .reg .u64 t; cvta.to.shared.u64 t, %1; cvt.u32.u64 %0, t; }" : "=r"(a) : "l"(p));
    return a;
}

// ---------------------------------------------------------------------------
// Tensor-core 64x64 tile GEMM body. 8 warps in 4(m) x 2(n); each warp owns
// 16m x 32n via 4 n-iterations of m16n8k8. A in smem [64][ASTRIDE] (m-major),
// B in smem [KC][72] (k-major). 3xTF32 per (A,B) fragment pair.
// acc[4][4]: [n-iter][c-frag].
// ---------------------------------------------------------------------------
template<int KCHUNK, int ASTRIDE>
__device__ __forceinline__ void mma_loop(
    const float (*As)[ASTRIDE], const float (*Bs)[72], float acc[4][4])
{
    const int tid  = threadIdx.x;
    const int lane = tid & 31;
    const int g    = lane >> 2;      // 0..7
    const int t    = lane & 3;       // 0..3
    const int warp = tid >> 5;
    const int wm   = (warp >> 1) * 16;   // 0,16,32,48
    const int wn   = (warp & 1) * 32;    // 0,32

    #pragma unroll
    for (int k0 = 0; k0 < KCHUNK; k0 += 8) {
        // A fragment (m16 x k8), rows wm+g / wm+g+8, cols k0+t / k0+t+4
        float af0 = As[wm + g    ][k0 + t];
        float af1 = As[wm + g + 8][k0 + t];
        float af2 = As[wm + g    ][k0 + t + 4];
        float af3 = As[wm + g + 8][k0 + t + 4];
        uint32_t ah0, al0, ah1, al1, ah2, al2, ah3, al3;
        split_tf32(af0, ah0, al0); split_tf32(af1, ah1, al1);
        split_tf32(af2, ah2, al2); split_tf32(af3, ah3, al3);

        #pragma unroll
        for (int ni = 0; ni < 4; ++ni) {
            int nn = wn + ni * 8 + g;
            float bf0 = Bs[k0 + t    ][nn];
            float bf1 = Bs[k0 + t + 4][nn];
            uint32_t bh0, bl0, bh1, bl1;
            split_tf32(bf0, bh0, bl0); split_tf32(bf1, bh1, bl1);

            mma_tf32(acc[ni], ah0, ah1, ah2, ah3, bh0, bh1);
            mma_tf32(acc[ni], al0, al1, al2, al3, bh0, bh1);
            mma_tf32(acc[ni], ah0, ah1, ah2, ah3, bl0, bl1);
        }
    }
}

// Epilogue: C frag m16n8 -> rows wm+g, wm+g+8; cols 2t, 2t+1 -> red.v2 pairs.
__device__ __forceinline__ void epilogue_red(float* dst, int n0, float acc[4][4])
{
    const int tid  = threadIdx.x;
    const int lane = tid & 31;
    const int g    = lane >> 2;
    const int t    = lane & 3;
    const int warp = tid >> 5;
    const int wm   = (warp >> 1) * 16;
    const int wn   = (warp & 1) * 32;

    #pragma unroll
    for (int ni = 0; ni < 4; ++ni) {
        int col = n0 + wn + ni * 8 + 2 * t;
        redg_add2(dst + (wm + g    ) * C_DIM + col, acc[ni][0], acc[ni][1]);
        redg_add2(dst + (wm + g + 8) * C_DIM + col, acc[ni][2], acc[ni][3]);
    }
}

// GEMM1: cnn[64,2048] @ Wkv[:,768:1536], 384 blocks -> g_v.
// Prologue (first 192 blocks): g_y = bias.
__global__ void __launch_bounds__(256, 2)
gemm1_kernel(const float* __restrict__ cnn, const float* __restrict__ Wkv,
             const float* __restrict__ bp)
{
    __shared__ float As[64][68];    // [m][k], 17.4 KB
    __shared__ float Bs[KC1][72];   // [k][n], 18.4 KB

    const int tid = threadIdx.x;
    if (blockIdx.x < 192 && tid < 64) {
        int idx = blockIdx.x * 64 + tid;                  // 12288 float4 of g_y
        ((float4*)g_y)[idx] = ((const float4*)bp)[idx % (C_DIM / 4)];
    }

    int ntile = blockIdx.x % NT1;
    int split = blockIdx.x / NT1;
    int n0 = ntile * 64;
    const float* A  = cnn + split * KC1;                                 // lda K1
    const float* Bm = Wkv + (size_t)(split * KC1) * LDKV + C_DIM + n0;   // ldb LDKV

    // One-phase staging: 1024 float4 per operand, 4 per thread, MLP=8.
    float4 aR[4], bR[4];
    #pragma unroll
    for (int i = 0; i < 4; ++i) {
        int idx = tid + i * 256;
        int am = idx / (KC1 / 4);
        int ak = (idx % (KC1 / 4)) * 4;
        aR[i] = *(const float4*)&A[am * K1 + ak];
        int bk = idx >> 4;
        int bn = (idx & 15) * 4;
        bR[i] = *(const float4*)&Bm[bk * LDKV + bn];
    }
    #pragma unroll
    for (int i = 0; i < 4; ++i) {
        int idx = tid + i * 256;
        int am = idx / (KC1 / 4);
        int ak = (idx % (KC1 / 4)) * 4;
        *(float4*)&As[am][ak] = aR[i];          // m-major, no transpose
        int bk = idx >> 4;
        int bn = (idx & 15) * 4;
        *(float4*)&Bs[bk][bn] = bR[i];
    }
    __syncthreads();

    float acc[4][4];
    #pragma unroll
    for (int i = 0; i < 4; ++i)
        #pragma unroll
        for (int j = 0; j < 4; ++j) acc[i][j] = 0.f;

    mma_loop<KC1, 68>(As, Bs, acc);
    epilogue_red(g_v, n0, acc);

    if (tid == 0) cudaTriggerProgrammaticLaunchCompletion();
}

// GEMM2: v[64,768] @ Wp, 192 blocks -> g_y (bias preloaded).
// PDL: Wp loads before the dependency sync; g_v loads after.
__global__ void __launch_bounds__(256, 2)
gemm2_kernel(const float* __restrict__ Wp)
{
    __shared__ float As[64][52];    // [m][k<=48], 13.3 KB
    __shared__ float Bs[KC2][72];   // 13.8 KB

    const int tid = threadIdx.x;
    int ntile = blockIdx.x % NT2;
    int split = blockIdx.x / NT2;
    int n0 = ntile * 64;
    const float* Bm = Wp + (size_t)(split * KC2) * C_DIM + n0;

    // pre-sync: Wp tile (768 float4, 3 per thread)
    float4 bR[3];
    #pragma unroll
    for (int i = 0; i < 3; ++i) {
        int idx = tid + i * 256;
        int bk = idx >> 4;
        int bn = (idx & 15) * 4;
        bR[i] = *(const float4*)&Bm[bk * C_DIM + bn];
    }

    cudaGridDependencySynchronize();       // wait for gemm1's g_v

    const float* A = g_v + split * KC2;
    float4 aR[3];
    #pragma unroll
    for (int i = 0; i < 3; ++i) {
        int idx = tid + i * 256;
        int am = idx / (KC2 / 4);
        int ak = (idx % (KC2 / 4)) * 4;
        aR[i] = *(const float4*)&A[am * C_DIM + ak];
    }
    #pragma unroll
    for (int i = 0; i < 3; ++i) {
        int idx = tid + i * 256;
        int am = idx / (KC2 / 4);
        int ak = (idx % (KC2 / 4)) * 4;
        *(float4*)&As[am][ak] = aR[i];
        int bk = idx >> 4;
        int bn = (idx & 15) * 4;
        *(float4*)&Bs[bk][bn] = bR[i];
    }
    __syncthreads();

    float acc[4][4];
    #pragma unroll
    for (int i = 0; i < 4; ++i)
        #pragma unroll
        for (int j = 0; j < 4; ++j) acc[i][j] = 0.f;

    mma_loop<KC2, 52>(As, Bs, acc);
    epilogue_red(g_y, n0, acc);

    if (tid == 0) cudaTriggerProgrammaticLaunchCompletion();
}

// Broadcast g_y over N=576 via TMA bulk stores; zero g_v for the next call.
// 576 blocks x 512 threads; PDL-synced against gemm2.
__global__ void __launch_bounds__(512)
bcast_kernel(float* __restrict__ out)
{
    __shared__ __align__(16) float ys[8 * C_DIM];   // 24 KB

    int b     = blockIdx.x / 9;
    int chunk = blockIdx.x % 9;
    const int tid = threadIdx.x;

    cudaGridDependencySynchronize();       // wait for gemm2's g_y

    const float4* ysrc = (const float4*)(g_y + b * C_DIM);
    #pragma unroll
    for (int i = tid; i < 8 * (C_DIM / 4); i += 512)
        ((float4*)ys)[i] = ysrc[i % (C_DIM / 4)];
    __syncthreads();
    asm volatile("fence.proxy.async.shared::cta;" ::: "memory");

    if (tid < 8) {
        uint32_t s = smem_u32(ys);
        float* g = out + ((size_t)b * N_SEQ + chunk * 64 + tid * 8) * C_DIM;
        asm volatile("cp.async.bulk.global.shared::cta.bulk_group [%0], [%1], %2;"
                     :: "l"(g), "r"(s), "n"(8 * C_DIM * 4) : "memory");
        asm volatile("cp.async.bulk.commit_group;" ::: "memory");
        asm volatile("cp.async.bulk.wait_group 0;" ::: "memory");
    }

    // zero g_v for the next call (first 192 blocks cover 12288 float4)
    if (blockIdx.x < 192 && tid < 64) {
        ((float4*)g_v)[blockIdx.x * 64 + tid] = make_float4(0.f, 0.f, 0.f, 0.f);
    }
}

extern "C" void kernel_launch(void* const* d_in, const int* in_sizes, int n_in,
                              void* d_out, int out_size)
{
    (void)in_sizes; (void)n_in; (void)out_size;
    // Inputs: image_patches, cnn_feature_vector, Wq, Wkv, Wp, bp
    const float* cnn = (const float*)d_in[1];
    const float* Wkv = (const float*)d_in[3];
    const float* Wp  = (const float*)d_in[4];
    const float* bp  = (const float*)d_in[5];
    float* out = (float*)d_out;

    gemm1_kernel<<<NT1 * KS1, 256>>>(cnn, Wkv, bp);   // 384 blocks

    cudaLaunchAttribute attr[1];
    attr[0].id = cudaLaunchAttributeProgrammaticStreamSerialization;
    attr[0].val.programmaticStreamSerializationAllowed = 1;

    {   // gemm2 with PDL
        cudaLaunchConfig_t cfg = {};
        cfg.gridDim  = dim3(NT2 * KS2, 1, 1);          // 192 blocks
        cfg.blockDim = dim3(256, 1, 1);
        cfg.attrs = attr;
        cfg.numAttrs = 1;
        cudaLaunchKernelEx(&cfg, gemm2_kernel, Wp);
    }
    {   // bcast with PDL
        cudaLaunchConfig_t cfg = {};
        cfg.gridDim  = dim3(B_SZ * 9, 1, 1);           // 576 blocks
        cfg.blockDim = dim3(512, 1, 1);
        cfg.attrs = attr;
        cfg.numAttrs = 1;
        cudaLaunchKernelEx(&cfg, bcast_kernel, out);
    }
}